// round 1
// baseline (speedup 1.0000x reference)
#include <cuda_runtime.h>

#define NB     256
#define NODES  116
#define FEAT   115
#define HID    128
#define LENN   6670
#define SEG2   13456
#define HC     512
#define STRIDE 116          // row stride (floats) for S, X, Xa; 116*4=464B = 29*16 -> float4 aligned

// smem layout in floats
#define OFF_S    0
#define OFF_X    13456
#define OFF_XA   26912
#define OFF_W    40368      // *4 = 161472, 16B aligned
#define OFF_DINV 55088
#define SM_FLOATS 55208
#define SMEM_BYTES (SM_FLOATS * 4)   // 220832 B < 227KB limit

__device__ float g_feat[NB * 2 * NODES];   // [256][232] staging for the MLP

__global__ void __launch_bounds__(256, 1)
gcn_kernel(const float* __restrict__ x,
           const int*   __restrict__ ei,
           const float* __restrict__ ew,
           const float* __restrict__ W1, const float* __restrict__ b1,
           const float* __restrict__ W2, const float* __restrict__ b2)
{
    extern __shared__ float sm[];
    float* sS    = sm + OFF_S;
    float* sX    = sm + OFF_X;
    float* sXa   = sm + OFF_XA;
    float* sW    = sm + OFF_W;
    float* sDinv = sm + OFF_DINV;

    const int g   = blockIdx.x >> 1;
    const int v   = blockIdx.x & 1;
    const int tid = threadIdx.x;
    const int wid = tid >> 5;
    const int lane = tid & 31;

    const float* W  = v ? W2 : W1;
    const float* bb = v ? b2 : b1;

    const float4 z4 = make_float4(0.f, 0.f, 0.f, 0.f);

    // ---- Phase 0: zero S, stage W and X into smem ----
    for (int i = tid; i < 13456 / 4; i += 256) ((float4*)sS)[i] = z4;
    for (int i = tid; i < (FEAT * HID) / 4; i += 256)
        ((float4*)sW)[i] = ((const float4*)W)[i];

    const float* xg = x + (size_t)(g * (2 * NODES) + v * NODES) * FEAT;
    for (int i = tid; i < NODES * FEAT; i += 256) {
        int r = i / FEAT;
        int c = i - r * FEAT;
        sX[r * STRIDE + c] = xg[i];
    }
    if (tid < NODES) sX[tid * STRIDE + FEAT] = 0.f;   // zero the pad column
    __syncthreads();

    // ---- Phase 1: scatter edges into S[dst][src] (unnormalized weights) ----
    {
        const int ebase = g * SEG2 + v * LENN;
        const int off   = g * (2 * NODES) + v * NODES;
        const int*   eis = ei + ebase;
        const int*   eid = ei + (NB * SEG2) + ebase;
        const float* ewp = ew + ebase;
        for (int e = tid; e < LENN; e += 256) {
            int s = eis[e] - off;
            int d = eid[e] - off;
            atomicAdd(&sS[d * STRIDE + s], ewp[e]);
        }
    }
    __syncthreads();

    // ---- Phase 2: deg[i] = rowsum(S[i]) + 1 ; dinv = rsqrt(deg) ----
    for (int r = wid; r < NODES; r += 8) {
        float s = sS[r * STRIDE + lane]
                + sS[r * STRIDE + 32 + lane]
                + sS[r * STRIDE + 64 + lane];
        if (lane < NODES - 96) s += sS[r * STRIDE + 96 + lane];
        #pragma unroll
        for (int o = 16; o; o >>= 1) s += __shfl_xor_sync(0xffffffffu, s, o);
        if (lane == 0) sDinv[r] = rsqrtf(s + 1.0f);
    }
    __syncthreads();

    // ---- Phase 3: S[i][j] = dinv_i * S0 * dinv_j (+ dinv_i^2 on diag) ----
    for (int i = tid; i < NODES * STRIDE; i += 256) {
        int r = i / STRIDE;
        int c = i - r * STRIDE;
        float val = sS[i] * sDinv[r] * sDinv[c];
        if (r == c) val += sDinv[r] * sDinv[r];
        sS[i] = val;
    }
    __syncthreads();

    // ---- Phase 4: Xa = S @ X   (4-row register tile per warp-pass) ----
    for (int t = wid; t < 29; t += 8) {
        const int i0 = t * 4;
        if (lane < 29) {
            float4 a0 = z4, a1 = z4, a2 = z4, a3 = z4;
            const float* s0p = sS + (i0 + 0) * STRIDE;
            const float* s1p = sS + (i0 + 1) * STRIDE;
            const float* s2p = sS + (i0 + 2) * STRIDE;
            const float* s3p = sS + (i0 + 3) * STRIDE;
            #pragma unroll 4
            for (int j = 0; j < NODES; j++) {
                float4 xv = ((const float4*)(sX + j * STRIDE))[lane];
                float s0 = s0p[j], s1 = s1p[j], s2 = s2p[j], s3 = s3p[j];
                a0.x = fmaf(s0, xv.x, a0.x); a0.y = fmaf(s0, xv.y, a0.y);
                a0.z = fmaf(s0, xv.z, a0.z); a0.w = fmaf(s0, xv.w, a0.w);
                a1.x = fmaf(s1, xv.x, a1.x); a1.y = fmaf(s1, xv.y, a1.y);
                a1.z = fmaf(s1, xv.z, a1.z); a1.w = fmaf(s1, xv.w, a1.w);
                a2.x = fmaf(s2, xv.x, a2.x); a2.y = fmaf(s2, xv.y, a2.y);
                a2.z = fmaf(s2, xv.z, a2.z); a2.w = fmaf(s2, xv.w, a2.w);
                a3.x = fmaf(s3, xv.x, a3.x); a3.y = fmaf(s3, xv.y, a3.y);
                a3.z = fmaf(s3, xv.z, a3.z); a3.w = fmaf(s3, xv.w, a3.w);
            }
            ((float4*)(sXa + (i0 + 0) * STRIDE))[lane] = a0;
            ((float4*)(sXa + (i0 + 1) * STRIDE))[lane] = a1;
            ((float4*)(sXa + (i0 + 2) * STRIDE))[lane] = a2;
            ((float4*)(sXa + (i0 + 3) * STRIDE))[lane] = a3;
        }
    }
    __syncthreads();

    // ---- Phase 5: out-row = Xa @ W + b, fold channel-max, write feat ----
    for (int t = wid; t < 29; t += 8) {
        const int i0 = t * 4;
        float4 a0 = z4, a1 = z4, a2 = z4, a3 = z4;
        const float* x0p = sXa + (i0 + 0) * STRIDE;
        const float* x1p = sXa + (i0 + 1) * STRIDE;
        const float* x2p = sXa + (i0 + 2) * STRIDE;
        const float* x3p = sXa + (i0 + 3) * STRIDE;
        #pragma unroll 4
        for (int k = 0; k < FEAT; k++) {
            float4 wv = ((const float4*)(sW + k * HID))[lane];
            float x0 = x0p[k], x1 = x1p[k], x2 = x2p[k], x3 = x3p[k];
            a0.x = fmaf(x0, wv.x, a0.x); a0.y = fmaf(x0, wv.y, a0.y);
            a0.z = fmaf(x0, wv.z, a0.z); a0.w = fmaf(x0, wv.w, a0.w);
            a1.x = fmaf(x1, wv.x, a1.x); a1.y = fmaf(x1, wv.y, a1.y);
            a1.z = fmaf(x1, wv.z, a1.z); a1.w = fmaf(x1, wv.w, a1.w);
            a2.x = fmaf(x2, wv.x, a2.x); a2.y = fmaf(x2, wv.y, a2.y);
            a2.z = fmaf(x2, wv.z, a2.z); a2.w = fmaf(x2, wv.w, a2.w);
            a3.x = fmaf(x3, wv.x, a3.x); a3.y = fmaf(x3, wv.y, a3.y);
            a3.z = fmaf(x3, wv.z, a3.z); a3.w = fmaf(x3, wv.w, a3.w);
        }
        float4 bv = ((const float4*)bb)[lane];
        a0.x += bv.x; a0.y += bv.y; a0.z += bv.z; a0.w += bv.w;
        a1.x += bv.x; a1.y += bv.y; a1.z += bv.z; a1.w += bv.w;
        a2.x += bv.x; a2.y += bv.y; a2.z += bv.z; a2.w += bv.w;
        a3.x += bv.x; a3.y += bv.y; a3.z += bv.z; a3.w += bv.w;

        float m0 = fmaxf(fmaxf(a0.x, a0.y), fmaxf(a0.z, a0.w));
        float m1 = fmaxf(fmaxf(a1.x, a1.y), fmaxf(a1.z, a1.w));
        float m2 = fmaxf(fmaxf(a2.x, a2.y), fmaxf(a2.z, a2.w));
        float m3 = fmaxf(fmaxf(a3.x, a3.y), fmaxf(a3.z, a3.w));
        #pragma unroll
        for (int o = 16; o; o >>= 1) {
            m0 = fmaxf(m0, __shfl_xor_sync(0xffffffffu, m0, o));
            m1 = fmaxf(m1, __shfl_xor_sync(0xffffffffu, m1, o));
            m2 = fmaxf(m2, __shfl_xor_sync(0xffffffffu, m2, o));
            m3 = fmaxf(m3, __shfl_xor_sync(0xffffffffu, m3, o));
        }
        if (lane == 0) {
            float* f = g_feat + g * (2 * NODES) + v;
            f[2 * (i0 + 0)] = m0;
            f[2 * (i0 + 1)] = m1;
            f[2 * (i0 + 2)] = m2;
            f[2 * (i0 + 3)] = m3;
        }
    }
}

// ---- MLP: out[g] = relu(feat[g] @ W6 + b6) @ W7 + b7 ----
// 32 CTAs x 8 graphs; weight-stationary over 8 feat rows held in smem.
__global__ void __launch_bounds__(256)
mlp_kernel(const float* __restrict__ W6, const float* __restrict__ b6,
           const float* __restrict__ W7, const float* __restrict__ b7,
           float* __restrict__ out)
{
    __shared__ float sF[8 * 232];
    __shared__ float sAcc[8];
    const int tid = threadIdx.x;
    const int g0 = blockIdx.x * 8;

    for (int i = tid; i < 8 * 232; i += 256) sF[i] = g_feat[g0 * 232 + i];
    if (tid < 8) sAcc[tid] = 0.f;
    __syncthreads();

    const int c0 = tid, c1 = tid + 256;
    float acc0[8], acc1[8];
    #pragma unroll
    for (int g = 0; g < 8; g++) { acc0[g] = 0.f; acc1[g] = 0.f; }

    #pragma unroll 4
    for (int k = 0; k < 232; k++) {
        float w0 = W6[k * HC + c0];
        float w1 = W6[k * HC + c1];
        #pragma unroll
        for (int g = 0; g < 8; g++) {
            float f = sF[g * 232 + k];
            acc0[g] = fmaf(f, w0, acc0[g]);
            acc1[g] = fmaf(f, w1, acc1[g]);
        }
    }

    const float bb0 = b6[c0], bb1 = b6[c1];
    const float w70 = W7[c0], w71 = W7[c1];
    #pragma unroll
    for (int g = 0; g < 8; g++) {
        float h0 = fmaxf(acc0[g] + bb0, 0.f);
        float h1 = fmaxf(acc1[g] + bb1, 0.f);
        float p = fmaf(h0, w70, h1 * w71);
        #pragma unroll
        for (int o = 16; o; o >>= 1) p += __shfl_xor_sync(0xffffffffu, p, o);
        if ((tid & 31) == 0) atomicAdd(&sAcc[g], p);
    }
    __syncthreads();
    if (tid < 8) out[g0 + tid] = sAcc[tid] + b7[0];
}

extern "C" void kernel_launch(void* const* d_in, const int* in_sizes, int n_in,
                              void* d_out, int out_size)
{
    const float* x  = (const float*)d_in[0];
    const int*   ei = (const int*)  d_in[1];
    const float* ew = (const float*)d_in[2];
    // d_in[3] = batch (unused)
    const float* W1 = (const float*)d_in[4];
    const float* b1 = (const float*)d_in[5];
    const float* W2 = (const float*)d_in[6];
    const float* b2 = (const float*)d_in[7];
    const float* W6 = (const float*)d_in[8];
    const float* b6 = (const float*)d_in[9];
    const float* W7 = (const float*)d_in[10];
    const float* b7 = (const float*)d_in[11];

    cudaFuncSetAttribute(gcn_kernel, cudaFuncAttributeMaxDynamicSharedMemorySize, SMEM_BYTES);

    gcn_kernel<<<2 * NB, 256, SMEM_BYTES>>>(x, ei, ew, W1, b1, W2, b2);
    mlp_kernel<<<NB / 8, 256>>>(W6, b6, W7, b7, (float*)d_out);
}

// round 2
// speedup vs baseline: 1.0286x; 1.0286x over previous
#include <cuda_runtime.h>

#define NB     256
#define NODES  116
#define FEAT   115
#define HID    128
#define LENN   6670
#define SEG2   13456
#define HC     512
#define STR    116           // row stride (floats) for S and X; 116*4B = 29 float4
#define NK4    29            // 116/4

// smem layout (floats)
#define OFF_S    0                    // 116*116 = 13456
#define OFF_X    13456                // 116*116 (padded col 115 = 0)
#define OFF_H    26912                // 116*128 = 14848
#define OFF_W    41760                // 116*128 (row 115 zeroed)
#define OFF_DINV 56608                // 116
#define SM_FLOATS 56724
#define SMEM_BYTES (SM_FLOATS * 4)    // 226896 B < 227KB

__device__ float g_feat[NB * 2 * NODES];   // [256][232]

// ---- H[i0..i0+R-1][0..127] = X @ W ------------------------------------
template<int R>
__device__ __forceinline__ void gemmA_tile(const float* sX, const float* sW,
                                           float* sH, int i0, int lane)
{
    float4 acc[R];
    #pragma unroll
    for (int r = 0; r < R; r++) acc[r] = make_float4(0.f, 0.f, 0.f, 0.f);
    for (int k4 = 0; k4 < NK4; k4++) {
        float4 wv0 = ((const float4*)(sW + (4*k4+0)*HID))[lane];
        float4 wv1 = ((const float4*)(sW + (4*k4+1)*HID))[lane];
        float4 wv2 = ((const float4*)(sW + (4*k4+2)*HID))[lane];
        float4 wv3 = ((const float4*)(sW + (4*k4+3)*HID))[lane];
        #pragma unroll
        for (int r = 0; r < R; r++) {
            float4 xk = ((const float4*)(sX + (i0+r)*STR))[k4];
            acc[r].x = fmaf(xk.x, wv0.x, acc[r].x); acc[r].y = fmaf(xk.x, wv0.y, acc[r].y);
            acc[r].z = fmaf(xk.x, wv0.z, acc[r].z); acc[r].w = fmaf(xk.x, wv0.w, acc[r].w);
            acc[r].x = fmaf(xk.y, wv1.x, acc[r].x); acc[r].y = fmaf(xk.y, wv1.y, acc[r].y);
            acc[r].z = fmaf(xk.y, wv1.z, acc[r].z); acc[r].w = fmaf(xk.y, wv1.w, acc[r].w);
            acc[r].x = fmaf(xk.z, wv2.x, acc[r].x); acc[r].y = fmaf(xk.z, wv2.y, acc[r].y);
            acc[r].z = fmaf(xk.z, wv2.z, acc[r].z); acc[r].w = fmaf(xk.z, wv2.w, acc[r].w);
            acc[r].x = fmaf(xk.w, wv3.x, acc[r].x); acc[r].y = fmaf(xk.w, wv3.y, acc[r].y);
            acc[r].z = fmaf(xk.w, wv3.z, acc[r].z); acc[r].w = fmaf(xk.w, wv3.w, acc[r].w);
        }
    }
    #pragma unroll
    for (int r = 0; r < R; r++)
        ((float4*)(sH + (i0+r)*HID))[lane] = acc[r];
}

// ---- rows i0..i0+R-1 of S@H + b, channel-max, write feat --------------
template<int R>
__device__ __forceinline__ void gemmB_tile(const float* sS, const float* sH,
                                           const float* bb, float* gout,
                                           int i0, int lane)
{
    float4 acc[R];
    #pragma unroll
    for (int r = 0; r < R; r++) acc[r] = make_float4(0.f, 0.f, 0.f, 0.f);
    for (int k4 = 0; k4 < NK4; k4++) {
        float4 hv0 = ((const float4*)(sH + (4*k4+0)*HID))[lane];
        float4 hv1 = ((const float4*)(sH + (4*k4+1)*HID))[lane];
        float4 hv2 = ((const float4*)(sH + (4*k4+2)*HID))[lane];
        float4 hv3 = ((const float4*)(sH + (4*k4+3)*HID))[lane];
        #pragma unroll
        for (int r = 0; r < R; r++) {
            float4 sk = ((const float4*)(sS + (i0+r)*STR))[k4];
            acc[r].x = fmaf(sk.x, hv0.x, acc[r].x); acc[r].y = fmaf(sk.x, hv0.y, acc[r].y);
            acc[r].z = fmaf(sk.x, hv0.z, acc[r].z); acc[r].w = fmaf(sk.x, hv0.w, acc[r].w);
            acc[r].x = fmaf(sk.y, hv1.x, acc[r].x); acc[r].y = fmaf(sk.y, hv1.y, acc[r].y);
            acc[r].z = fmaf(sk.y, hv1.z, acc[r].z); acc[r].w = fmaf(sk.y, hv1.w, acc[r].w);
            acc[r].x = fmaf(sk.z, hv2.x, acc[r].x); acc[r].y = fmaf(sk.z, hv2.y, acc[r].y);
            acc[r].z = fmaf(sk.z, hv2.z, acc[r].z); acc[r].w = fmaf(sk.z, hv2.w, acc[r].w);
            acc[r].x = fmaf(sk.w, hv3.x, acc[r].x); acc[r].y = fmaf(sk.w, hv3.y, acc[r].y);
            acc[r].z = fmaf(sk.w, hv3.z, acc[r].z); acc[r].w = fmaf(sk.w, hv3.w, acc[r].w);
        }
    }
    float4 bv = ((const float4*)bb)[lane];
    #pragma unroll
    for (int r = 0; r < R; r++) {
        float m = fmaxf(fmaxf(acc[r].x + bv.x, acc[r].y + bv.y),
                        fmaxf(acc[r].z + bv.z, acc[r].w + bv.w));
        #pragma unroll
        for (int o = 16; o; o >>= 1) m = fmaxf(m, __shfl_xor_sync(0xffffffffu, m, o));
        if (lane == 0) gout[2 * (i0 + r)] = m;
    }
}

__global__ void __launch_bounds__(256, 1)
gcn_kernel(const float* __restrict__ x,
           const int*   __restrict__ ei,
           const float* __restrict__ ew,
           const float* __restrict__ W1, const float* __restrict__ b1,
           const float* __restrict__ W2, const float* __restrict__ b2)
{
    extern __shared__ float sm[];
    float* sS    = sm + OFF_S;
    float* sX    = sm + OFF_X;
    float* sH    = sm + OFF_H;
    float* sW    = sm + OFF_W;
    float* sDinv = sm + OFF_DINV;

    const int g    = blockIdx.x >> 1;
    const int v    = blockIdx.x & 1;
    const int tid  = threadIdx.x;
    const int wid  = tid >> 5;
    const int lane = tid & 31;

    const float* W  = v ? W2 : W1;
    const float* bb = v ? b2 : b1;
    const float4 z4 = make_float4(0.f, 0.f, 0.f, 0.f);

    // ---- Phase 0: zero S, stage W and X in smem ----
    for (int i = tid; i < 13456 / 4; i += 256) ((float4*)sS)[i] = z4;
    for (int i = tid; i < (FEAT * HID) / 4; i += 256)
        ((float4*)sW)[i] = ((const float4*)W)[i];
    if (tid < HID) sW[FEAT * HID + tid] = 0.f;     // pad row 115 of W

    const float* xg = x + (size_t)(g * (2 * NODES) + v * NODES) * FEAT;
    for (int i = tid; i < NODES * FEAT; i += 256) {
        int r = i / FEAT;
        int c = i - r * FEAT;
        sX[r * STR + c] = xg[i];
    }
    if (tid < NODES) sX[tid * STR + FEAT] = 0.f;   // pad col 115 of X
    __syncthreads();

    // ---- Phase 1 (specialized): warps 0-1 scatter edges; warps 2-7 do H=X@W ----
    if (wid < 2) {
        const int ebase = g * SEG2 + v * LENN;
        const int off   = g * (2 * NODES) + v * NODES;
        const int*   eis = ei + ebase;
        const int*   eid = ei + (NB * SEG2) + ebase;
        const float* ewp = ew + ebase;
        #pragma unroll 4
        for (int e = tid; e < LENN; e += 64) {
            int s = eis[e] - off;
            int d = eid[e] - off;
            atomicAdd(&sS[d * STR + s], ewp[e]);
        }
    } else {
        for (int t = wid - 2; t < 14; t += 6)
            gemmA_tile<8>(sX, sW, sH, t * 8, lane);
        if (wid == 4)
            gemmA_tile<4>(sX, sW, sH, 112, lane);
    }
    __syncthreads();

    // ---- Phase 2: dinv[i] = rsqrt(rowsum(S[i]) + 1) ----
    for (int r = wid; r < NODES; r += 8) {
        float s = sS[r * STR + lane]
                + sS[r * STR + 32 + lane]
                + sS[r * STR + 64 + lane];
        if (lane < NODES - 96) s += sS[r * STR + 96 + lane];
        #pragma unroll
        for (int o = 16; o; o >>= 1) s += __shfl_xor_sync(0xffffffffu, s, o);
        if (lane == 0) sDinv[r] = rsqrtf(s + 1.0f);
    }
    __syncthreads();

    // ---- Phase 3: normalize S + self-loop diag (float4-wide) ----
    for (int idx = tid; idx < NODES * NK4; idx += 256) {
        int r  = idx / NK4;
        int c4 = idx - r * NK4;
        float4 s  = ((float4*)sS)[idx];
        float  di = sDinv[r];
        float4 dj = ((const float4*)sDinv)[c4];
        s.x *= di * dj.x; s.y *= di * dj.y; s.z *= di * dj.z; s.w *= di * dj.w;
        int c0 = c4 * 4;
        if (r - c0 >= 0 && r - c0 < 4) {
            float d2 = di * di;
            if (r == c0)     s.x += d2;
            if (r == c0 + 1) s.y += d2;
            if (r == c0 + 2) s.z += d2;
            if (r == c0 + 3) s.w += d2;
        }
        ((float4*)sS)[idx] = s;
    }
    __syncthreads();

    // ---- Phase B: out = S@H + b, fused channel-max, write feat ----
    float* gout = g_feat + g * (2 * NODES) + v;
    for (int t = wid; t < 14; t += 8)
        gemmB_tile<8>(sS, sH, bb, gout, t * 8, lane);
    if (wid == 6)
        gemmB_tile<4>(sS, sH, bb, gout, 112, lane);
}

// ---- MLP: out[g] = relu(feat[g] @ W6 + b6) @ W7 + b7 ----
// 128 CTAs x 2 graphs, 256 threads: thread owns cols tid and tid+256.
__global__ void __launch_bounds__(256)
mlp_kernel(const float* __restrict__ W6, const float* __restrict__ b6,
           const float* __restrict__ W7, const float* __restrict__ b7,
           float* __restrict__ out)
{
    __shared__ float sF[2 * 232];
    __shared__ float sAcc[2];
    const int tid = threadIdx.x;
    const int g0  = blockIdx.x * 2;

    for (int i = tid; i < 2 * 232; i += 256) sF[i] = g_feat[g0 * 232 + i];
    if (tid < 2) sAcc[tid] = 0.f;
    __syncthreads();

    float a00 = 0.f, a01 = 0.f, a10 = 0.f, a11 = 0.f;
    #pragma unroll 8
    for (int k = 0; k < 232; k++) {
        float w0 = W6[k * HC + tid];
        float w1 = W6[k * HC + 256 + tid];
        float f0 = sF[k];
        float f1 = sF[232 + k];
        a00 = fmaf(f0, w0, a00); a01 = fmaf(f0, w1, a01);
        a10 = fmaf(f1, w0, a10); a11 = fmaf(f1, w1, a11);
    }

    const float b60 = b6[tid], b61 = b6[tid + 256];
    const float w70 = W7[tid], w71 = W7[tid + 256];
    {
        float h0 = fmaxf(a00 + b60, 0.f);
        float h1 = fmaxf(a01 + b61, 0.f);
        float p  = fmaf(h0, w70, h1 * w71);
        #pragma unroll
        for (int o = 16; o; o >>= 1) p += __shfl_xor_sync(0xffffffffu, p, o);
        if ((tid & 31) == 0) atomicAdd(&sAcc[0], p);
    }
    {
        float h0 = fmaxf(a10 + b60, 0.f);
        float h1 = fmaxf(a11 + b61, 0.f);
        float p  = fmaf(h0, w70, h1 * w71);
        #pragma unroll
        for (int o = 16; o; o >>= 1) p += __shfl_xor_sync(0xffffffffu, p, o);
        if ((tid & 31) == 0) atomicAdd(&sAcc[1], p);
    }
    __syncthreads();
    if (tid < 2) out[g0 + tid] = sAcc[tid] + b7[0];
}

extern "C" void kernel_launch(void* const* d_in, const int* in_sizes, int n_in,
                              void* d_out, int out_size)
{
    const float* x  = (const float*)d_in[0];
    const int*   ei = (const int*)  d_in[1];
    const float* ew = (const float*)d_in[2];
    // d_in[3] = batch (unused)
    const float* W1 = (const float*)d_in[4];
    const float* b1 = (const float*)d_in[5];
    const float* W2 = (const float*)d_in[6];
    const float* b2 = (const float*)d_in[7];
    const float* W6 = (const float*)d_in[8];
    const float* b6 = (const float*)d_in[9];
    const float* W7 = (const float*)d_in[10];
    const float* b7 = (const float*)d_in[11];

    cudaFuncSetAttribute(gcn_kernel, cudaFuncAttributeMaxDynamicSharedMemorySize, SMEM_BYTES);

    gcn_kernel<<<2 * NB, 256, SMEM_BYTES>>>(x, ei, ew, W1, b1, W2, b2);
    mlp_kernel<<<NB / 2, 256>>>(W6, b6, W7, b7, (float*)d_out);
}

// round 3
// speedup vs baseline: 1.3095x; 1.2731x over previous
#include <cuda_runtime.h>

#define NB     256
#define NODES  116
#define FEAT   115
#define HID    128
#define LENN   6670
#define SEG2   13456
#define HC     512
#define STR    116           // row stride (floats) for S and X
#define NK4    29            // 116/4

// smem layout (floats)
#define OFF_S    0                    // 116*116 = 13456
#define OFF_X    13456                // 116*116 (padded col 115 = 0)
#define OFF_H    26912                // 116*128 = 14848
#define OFF_W    41760                // 116*128 (row 115 zeroed)
#define OFF_DINV 56608                // 116
#define SM_FLOATS 56724
#define SMEM_BYTES (SM_FLOATS * 4)    // 226896 B < 227KB

typedef unsigned long long ull;

__device__ float g_feat[NB * 2 * NODES];   // [256][232]

// ---- packed fp32x2 helpers (Blackwell sm_103a) ----
__device__ __forceinline__ ull pack2(float s) {
    ull r; asm("mov.b64 %0, {%1, %1};" : "=l"(r) : "f"(s)); return r;
}
__device__ __forceinline__ void ffma2(ull& d, ull a, ull b) {
    asm("fma.rn.f32x2 %0, %1, %2, %0;" : "+l"(d) : "l"(a), "l"(b));
}
__device__ __forceinline__ void unpack2(float& lo, float& hi, ull a) {
    asm("mov.b64 {%0, %1}, %2;" : "=f"(lo), "=f"(hi) : "l"(a));
}

// chunk partition: 16 chunks, sizes {8,8,8,8,7,7,7,7,7,7,7,7,7,7,7,7}
// warp w takes chunks w and w+8 -> every SMSP gets exactly 29 rows.
__device__ __forceinline__ int chunk_start(int c) { return c < 4 ? 8 * c : 32 + 7 * (c - 4); }

// ---- A-rows i0..i0+R-1:  Out[r][0..127] = Amat[r][:] @ Bmat  -----------
// Amat rows have stride astr (scalar per (r,k)); Bmat rows have stride HID.
template<int R>
__device__ __forceinline__ void gemm_tile(const float* Amat, int astr,
                                          const float* Bmat, ull* acc /*[R][2]*/,
                                          int i0, int lane)
{
    #pragma unroll
    for (int r = 0; r < 2 * R; r++) acc[r] = 0ull;
    for (int k4 = 0; k4 < NK4; k4++) {
        ulonglong2 w0 = ((const ulonglong2*)(Bmat + (4 * k4 + 0) * HID))[lane];
        ulonglong2 w1 = ((const ulonglong2*)(Bmat + (4 * k4 + 1) * HID))[lane];
        ulonglong2 w2 = ((const ulonglong2*)(Bmat + (4 * k4 + 2) * HID))[lane];
        ulonglong2 w3 = ((const ulonglong2*)(Bmat + (4 * k4 + 3) * HID))[lane];
        #pragma unroll
        for (int r = 0; r < R; r++) {
            float4 ak = ((const float4*)(Amat + (i0 + r) * astr))[k4];
            ull s0 = pack2(ak.x), s1 = pack2(ak.y), s2 = pack2(ak.z), s3 = pack2(ak.w);
            ffma2(acc[2*r+0], s0, w0.x); ffma2(acc[2*r+1], s0, w0.y);
            ffma2(acc[2*r+0], s1, w1.x); ffma2(acc[2*r+1], s1, w1.y);
            ffma2(acc[2*r+0], s2, w2.x); ffma2(acc[2*r+1], s2, w2.y);
            ffma2(acc[2*r+0], s3, w3.x); ffma2(acc[2*r+1], s3, w3.y);
        }
    }
}

template<int R>
__device__ __forceinline__ void gemmA_store(const float* sX, const float* sW,
                                            float* sH, int i0, int lane)
{
    ull acc[2 * R];
    gemm_tile<R>(sX, STR, sW, acc, i0, lane);
    #pragma unroll
    for (int r = 0; r < R; r++)
        ((ulonglong2*)(sH + (i0 + r) * HID))[lane] = make_ulonglong2(acc[2*r], acc[2*r+1]);
}

template<int R>
__device__ __forceinline__ void gemmB_max(const float* sS, const float* sH,
                                          const float* bb, float* gout,
                                          int i0, int lane)
{
    ull acc[2 * R];
    gemm_tile<R>(sS, STR, sH, acc, i0, lane);
    float4 bv = ((const float4*)bb)[lane];
    #pragma unroll
    for (int r = 0; r < R; r++) {
        float a0, a1, a2, a3;
        unpack2(a0, a1, acc[2*r]);
        unpack2(a2, a3, acc[2*r+1]);
        float m = fmaxf(fmaxf(a0 + bv.x, a1 + bv.y), fmaxf(a2 + bv.z, a3 + bv.w));
        #pragma unroll
        for (int o = 16; o; o >>= 1) m = fmaxf(m, __shfl_xor_sync(0xffffffffu, m, o));
        if (lane == 0) gout[2 * (i0 + r)] = m;
    }
}

__global__ void __launch_bounds__(256, 1)
gcn_kernel(const float* __restrict__ x,
           const int*   __restrict__ ei,
           const float* __restrict__ ew,
           const float* __restrict__ W1, const float* __restrict__ b1,
           const float* __restrict__ W2, const float* __restrict__ b2)
{
    extern __shared__ float sm[];
    float* sS    = sm + OFF_S;
    float* sX    = sm + OFF_X;
    float* sH    = sm + OFF_H;
    float* sW    = sm + OFF_W;
    float* sDinv = sm + OFF_DINV;

    const int g    = blockIdx.x >> 1;
    const int v    = blockIdx.x & 1;
    const int tid  = threadIdx.x;
    const int wid  = tid >> 5;
    const int lane = tid & 31;

    const float* W  = v ? W2 : W1;
    const float* bb = v ? b2 : b1;
    const float4 z4 = make_float4(0.f, 0.f, 0.f, 0.f);

    // ---- Phase 0: zero S, stage W and X in smem ----
    for (int i = tid; i < 13456 / 4; i += 256) ((float4*)sS)[i] = z4;
    for (int i = tid; i < (FEAT * HID) / 4; i += 256)
        ((float4*)sW)[i] = ((const float4*)W)[i];
    if (tid < HID) sW[FEAT * HID + tid] = 0.f;     // pad row 115 of W

    const float* xg = x + (size_t)(g * (2 * NODES) + v * NODES) * FEAT;
    for (int i = tid; i < NODES * FEAT; i += 256) {
        int r = i / FEAT;
        int c = i - r * FEAT;
        sX[r * STR + c] = xg[i];
    }
    if (tid < NODES) sX[tid * STR + FEAT] = 0.f;   // pad col 115 of X
    __syncthreads();

    // ---- Phase 1: all threads scatter edges into S[dst][src] ----
    {
        const int ebase = g * SEG2 + v * LENN;
        const int off   = g * (2 * NODES) + v * NODES;
        const int*   eis = ei + ebase;
        const int*   eid = ei + (NB * SEG2) + ebase;
        const float* ewp = ew + ebase;
        #pragma unroll 2
        for (int e = tid; e < LENN; e += 256) {
            int s = eis[e] - off;
            int d = eid[e] - off;
            atomicAdd(&sS[d * STR + s], ewp[e]);
        }
    }
    __syncthreads();

    // ---- Phase A: H = X @ W (balanced 16-chunk partition) ----
    {
        int c0 = wid, c1 = wid + 8;
        if (c0 < 4) gemmA_store<8>(sX, sW, sH, chunk_start(c0), lane);
        else        gemmA_store<7>(sX, sW, sH, chunk_start(c0), lane);
        gemmA_store<7>(sX, sW, sH, chunk_start(c1), lane);
    }

    // ---- Phase 2: dinv[i] = rsqrt(rowsum(S[i]) + 1) ----
    for (int r = wid; r < NODES; r += 8) {
        float s = sS[r * STR + lane]
                + sS[r * STR + 32 + lane]
                + sS[r * STR + 64 + lane];
        if (lane < NODES - 96) s += sS[r * STR + 96 + lane];
        #pragma unroll
        for (int o = 16; o; o >>= 1) s += __shfl_xor_sync(0xffffffffu, s, o);
        if (lane == 0) sDinv[r] = rsqrtf(s + 1.0f);
    }
    __syncthreads();

    // ---- Phase 3: normalize S + self-loop diag (float4-wide) ----
    for (int idx = tid; idx < NODES * NK4; idx += 256) {
        int r  = idx / NK4;
        int c4 = idx - r * NK4;
        float4 s  = ((float4*)sS)[idx];
        float  di = sDinv[r];
        float4 dj = ((const float4*)sDinv)[c4];
        s.x *= di * dj.x; s.y *= di * dj.y; s.z *= di * dj.z; s.w *= di * dj.w;
        int c0 = c4 * 4;
        if (r - c0 >= 0 && r - c0 < 4) {
            float d2 = di * di;
            if (r == c0)     s.x += d2;
            if (r == c0 + 1) s.y += d2;
            if (r == c0 + 2) s.z += d2;
            if (r == c0 + 3) s.w += d2;
        }
        ((float4*)sS)[idx] = s;
    }
    __syncthreads();

    // ---- Phase B: out = S@H + b, fused channel-max, write feat ----
    {
        float* gout = g_feat + g * (2 * NODES) + v;
        int c0 = wid, c1 = wid + 8;
        if (c0 < 4) gemmB_max<8>(sS, sH, bb, gout, chunk_start(c0), lane);
        else        gemmB_max<7>(sS, sH, bb, gout, chunk_start(c0), lane);
        gemmB_max<7>(sS, sH, bb, gout, chunk_start(c1), lane);
    }
}

// ---- MLP: out[g] = relu(feat[g] @ W6 + b6) @ W7 + b7 ----
// 128 CTAs x 2 graphs; thread owns 4 consecutive HC columns (float4 LDG).
__global__ void __launch_bounds__(256)
mlp_kernel(const float* __restrict__ W6, const float* __restrict__ b6,
           const float* __restrict__ W7, const float* __restrict__ b7,
           float* __restrict__ out)
{
    __shared__ float sF[2 * 232];
    __shared__ float sAcc[2];
    const int tid  = threadIdx.x;
    const int g0   = blockIdx.x * 2;
    const int gsel = tid >> 7;       // warps 0-3 -> graph 0, warps 4-7 -> graph 1
    const int cq   = tid & 127;      // float4 column group: cols 4cq..4cq+3

    for (int i = tid; i < 2 * 232; i += 256) sF[i] = g_feat[g0 * 232 + i];
    if (tid < 2) sAcc[tid] = 0.f;
    __syncthreads();

    const float* fp = sF + gsel * 232;
    float4 acc = make_float4(0.f, 0.f, 0.f, 0.f);
    #pragma unroll 8
    for (int k = 0; k < 232; k++) {
        float4 w = ((const float4*)(W6 + k * HC))[cq];
        float  f = fp[k];
        acc.x = fmaf(f, w.x, acc.x); acc.y = fmaf(f, w.y, acc.y);
        acc.z = fmaf(f, w.z, acc.z); acc.w = fmaf(f, w.w, acc.w);
    }

    float4 bv = ((const float4*)b6)[cq];
    float4 wv = ((const float4*)W7)[cq];
    float h0 = fmaxf(acc.x + bv.x, 0.f);
    float h1 = fmaxf(acc.y + bv.y, 0.f);
    float h2 = fmaxf(acc.z + bv.z, 0.f);
    float h3 = fmaxf(acc.w + bv.w, 0.f);
    float p = fmaf(h0, wv.x, fmaf(h1, wv.y, fmaf(h2, wv.z, h3 * wv.w)));
    #pragma unroll
    for (int o = 16; o; o >>= 1) p += __shfl_xor_sync(0xffffffffu, p, o);
    if ((tid & 31) == 0) atomicAdd(&sAcc[gsel], p);
    __syncthreads();
    if (tid < 2) out[g0 + tid] = sAcc[tid] + b7[0];
}

extern "C" void kernel_launch(void* const* d_in, const int* in_sizes, int n_in,
                              void* d_out, int out_size)
{
    const float* x  = (const float*)d_in[0];
    const int*   ei = (const int*)  d_in[1];
    const float* ew = (const float*)d_in[2];
    // d_in[3] = batch (unused)
    const float* W1 = (const float*)d_in[4];
    const float* b1 = (const float*)d_in[5];
    const float* W2 = (const float*)d_in[6];
    const float* b2 = (const float*)d_in[7];
    const float* W6 = (const float*)d_in[8];
    const float* b6 = (const float*)d_in[9];
    const float* W7 = (const float*)d_in[10];
    const float* b7 = (const float*)d_in[11];

    cudaFuncSetAttribute(gcn_kernel, cudaFuncAttributeMaxDynamicSharedMemorySize, SMEM_BYTES);

    gcn_kernel<<<2 * NB, 256, SMEM_BYTES>>>(x, ei, ew, W1, b1, W2, b2);
    mlp_kernel<<<NB / 2, 256>>>(W6, b6, W7, b7, (float*)d_out);
}

// round 4
// speedup vs baseline: 1.4977x; 1.1437x over previous
#include <cuda_runtime.h>

#define NB     256
#define NODES  116
#define FEAT   115
#define HID    128
#define LENN   6670
#define SEG2   13456
#define HC     512
#define STR    116           // row stride (floats) for S and X
#define NK4    29            // 116/4

// smem layout (floats)
#define OFF_S    0                    // 116*116 = 13456
#define OFF_X    13456                // 116*116 (padded col 115 = 0)
#define OFF_H    26912                // 116*128 = 14848
#define OFF_W    41760                // 116*128 (row 115 zeroed)
#define OFF_DINV 56608                // 116
#define SM_FLOATS 56724
#define SMEM_BYTES (SM_FLOATS * 4)    // 226896 B < 227KB

typedef unsigned long long ull;

__device__ float g_feat[NB * 2 * NODES];   // [256][232]

// ---- packed fp32x2 helpers (Blackwell sm_103a) ----
__device__ __forceinline__ ull pack2(float s) {
    ull r; asm("mov.b64 %0, {%1, %1};" : "=l"(r) : "f"(s)); return r;
}
__device__ __forceinline__ void ffma2(ull& d, ull a, ull b) {
    asm("fma.rn.f32x2 %0, %1, %2, %0;" : "+l"(d) : "l"(a), "l"(b));
}
__device__ __forceinline__ void unpack2(float& lo, float& hi, ull a) {
    asm("mov.b64 {%0, %1}, %2;" : "=f"(lo), "=f"(hi) : "l"(a));
}

// 8 chunks, sizes {15,15,15,15,14,14,14,14}; warp w takes chunk w.
// SMSP s gets warps s and s+4 -> 15+14 = 29 rows per SMSP per GEMM.
__device__ __forceinline__ int chunk_start(int c) { return c < 4 ? 15 * c : 60 + 14 * (c - 4); }

// ---- rows i0..i0+R-1:  Out[r][0..127] = Amat[r][:] @ Bmat ----
template<int R>
__device__ __forceinline__ void gemm_tile(const float* Amat, int astr,
                                          const float* Bmat, ull* acc /*[2R]*/,
                                          int i0, int lane)
{
    #pragma unroll
    for (int r = 0; r < 2 * R; r++) acc[r] = 0ull;
    for (int k4 = 0; k4 < NK4; k4++) {
        ulonglong2 w0 = ((const ulonglong2*)(Bmat + (4 * k4 + 0) * HID))[lane];
        ulonglong2 w1 = ((const ulonglong2*)(Bmat + (4 * k4 + 1) * HID))[lane];
        ulonglong2 w2 = ((const ulonglong2*)(Bmat + (4 * k4 + 2) * HID))[lane];
        ulonglong2 w3 = ((const ulonglong2*)(Bmat + (4 * k4 + 3) * HID))[lane];
        #pragma unroll
        for (int r = 0; r < R; r++) {
            float4 ak = ((const float4*)(Amat + (i0 + r) * astr))[k4];
            ull s0 = pack2(ak.x), s1 = pack2(ak.y), s2 = pack2(ak.z), s3 = pack2(ak.w);
            ffma2(acc[2*r+0], s0, w0.x); ffma2(acc[2*r+1], s0, w0.y);
            ffma2(acc[2*r+0], s1, w1.x); ffma2(acc[2*r+1], s1, w1.y);
            ffma2(acc[2*r+0], s2, w2.x); ffma2(acc[2*r+1], s2, w2.y);
            ffma2(acc[2*r+0], s3, w3.x); ffma2(acc[2*r+1], s3, w3.y);
        }
    }
}

template<int R>
__device__ __forceinline__ void gemmA_store(const float* sX, const float* sW,
                                            float* sH, int i0, int lane)
{
    ull acc[2 * R];
    gemm_tile<R>(sX, STR, sW, acc, i0, lane);
    #pragma unroll
    for (int r = 0; r < R; r++)
        ((ulonglong2*)(sH + (i0 + r) * HID))[lane] = make_ulonglong2(acc[2*r], acc[2*r+1]);
}

template<int R>
__device__ __forceinline__ void gemmB_max(const float* sS, const float* sH,
                                          const float* bb, float* gout,
                                          int i0, int lane)
{
    ull acc[2 * R];
    gemm_tile<R>(sS, STR, sH, acc, i0, lane);
    float4 bv = ((const float4*)bb)[lane];
    #pragma unroll
    for (int r = 0; r < R; r++) {
        float a0, a1, a2, a3;
        unpack2(a0, a1, acc[2*r]);
        unpack2(a2, a3, acc[2*r+1]);
        float m = fmaxf(fmaxf(a0 + bv.x, a1 + bv.y), fmaxf(a2 + bv.z, a3 + bv.w));
        #pragma unroll
        for (int o = 16; o; o >>= 1) m = fmaxf(m, __shfl_xor_sync(0xffffffffu, m, o));
        if (lane == 0) gout[2 * (i0 + r)] = m;
    }
}

__global__ void __launch_bounds__(256, 1)
gcn_kernel(const float* __restrict__ x,
           const int*   __restrict__ ei,
           const float* __restrict__ ew,
           const float* __restrict__ W1, const float* __restrict__ b1,
           const float* __restrict__ W2, const float* __restrict__ b2)
{
    extern __shared__ float sm[];
    float* sS    = sm + OFF_S;
    float* sX    = sm + OFF_X;
    float* sH    = sm + OFF_H;
    float* sW    = sm + OFF_W;
    float* sDinv = sm + OFF_DINV;

    const int g    = blockIdx.x >> 1;
    const int v    = blockIdx.x & 1;
    const int tid  = threadIdx.x;
    const int wid  = tid >> 5;
    const int lane = tid & 31;

    const float* W  = v ? W2 : W1;
    const float* bb = v ? b2 : b1;
    const float4 z4 = make_float4(0.f, 0.f, 0.f, 0.f);

    // ---- Phase 0: zero S, stage W and X in smem ----
    for (int i = tid; i < 13456 / 4; i += 256) ((float4*)sS)[i] = z4;
    for (int i = tid; i < (FEAT * HID) / 4; i += 256)
        ((float4*)sW)[i] = ((const float4*)W)[i];
    if (tid < HID) sW[FEAT * HID + tid] = 0.f;     // pad row 115 of W

    const float* xg = x + (size_t)(g * (2 * NODES) + v * NODES) * FEAT;
    for (int i = tid; i < NODES * FEAT; i += 256) {
        int r = i / FEAT;
        int c = i - r * FEAT;
        sX[r * STR + c] = xg[i];
    }
    if (tid < NODES) sX[tid * STR + FEAT] = 0.f;   // pad col 115 of X
    __syncthreads();

    // ---- Phase 1: scatter edges into S[dst][src], batched LDG x4 ----
    {
        const int ebase = g * SEG2 + v * LENN;
        const int off   = g * (2 * NODES) + v * NODES;
        const int*   eis = ei + ebase;
        const int*   eid = ei + (NB * SEG2) + ebase;
        const float* ewp = ew + ebase;
        const int nfull = (LENN / 1024) * 1024;   // 6144
        for (int e = tid; e < nfull; e += 1024) {
            int   s0 = eis[e],       s1 = eis[e + 256], s2 = eis[e + 512], s3 = eis[e + 768];
            int   d0 = eid[e],       d1 = eid[e + 256], d2 = eid[e + 512], d3 = eid[e + 768];
            float w0 = ewp[e],       w1 = ewp[e + 256], w2 = ewp[e + 512], w3 = ewp[e + 768];
            atomicAdd(&sS[(d0 - off) * STR + (s0 - off)], w0);
            atomicAdd(&sS[(d1 - off) * STR + (s1 - off)], w1);
            atomicAdd(&sS[(d2 - off) * STR + (s2 - off)], w2);
            atomicAdd(&sS[(d3 - off) * STR + (s3 - off)], w3);
        }
        for (int e = nfull + tid; e < LENN; e += 256) {
            int s = eis[e] - off;
            int d = eid[e] - off;
            atomicAdd(&sS[d * STR + s], ewp[e]);
        }
    }
    __syncthreads();

    // ---- Phase A: H = X @ W (one 15/14-row chunk per warp) ----
    if (wid < 4) gemmA_store<15>(sX, sW, sH, chunk_start(wid), lane);
    else         gemmA_store<14>(sX, sW, sH, chunk_start(wid), lane);

    // ---- Phase 2: dinv[i] = rsqrt(rowsum(S[i]) + 1) ----
    for (int r = wid; r < NODES; r += 8) {
        float s = sS[r * STR + lane]
                + sS[r * STR + 32 + lane]
                + sS[r * STR + 64 + lane];
        if (lane < NODES - 96) s += sS[r * STR + 96 + lane];
        #pragma unroll
        for (int o = 16; o; o >>= 1) s += __shfl_xor_sync(0xffffffffu, s, o);
        if (lane == 0) sDinv[r] = rsqrtf(s + 1.0f);
    }
    __syncthreads();

    // ---- Phase 3: normalize S + self-loop diag (float4-wide) ----
    for (int idx = tid; idx < NODES * NK4; idx += 256) {
        int r  = idx / NK4;
        int c4 = idx - r * NK4;
        float4 s  = ((float4*)sS)[idx];
        float  di = sDinv[r];
        float4 dj = ((const float4*)sDinv)[c4];
        s.x *= di * dj.x; s.y *= di * dj.y; s.z *= di * dj.z; s.w *= di * dj.w;
        int c0 = c4 * 4;
        if (r - c0 >= 0 && r - c0 < 4) {
            float d2 = di * di;
            if (r == c0)     s.x += d2;
            if (r == c0 + 1) s.y += d2;
            if (r == c0 + 2) s.z += d2;
            if (r == c0 + 3) s.w += d2;
        }
        ((float4*)sS)[idx] = s;
    }
    __syncthreads();

    // ---- Phase B: out = S@H + b, fused channel-max, write feat ----
    {
        float* gout = g_feat + g * (2 * NODES) + v;
        if (wid < 4) gemmB_max<15>(sS, sH, bb, gout, chunk_start(wid), lane);
        else         gemmB_max<14>(sS, sH, bb, gout, chunk_start(wid), lane);
    }
}

// ---- MLP: out[g] = relu(feat[g] @ W6 + b6) @ W7 + b7 ----
// 128 CTAs x 2 graphs. K split in halves across warp-groups; each thread
// carries BOTH graphs; manual k+=4 body forces MLP>=4 on the W6 loads.
__global__ void __launch_bounds__(256, 1)
mlp_kernel(const float* __restrict__ W6, const float* __restrict__ b6,
           const float* __restrict__ W7, const float* __restrict__ b7,
           float* __restrict__ out)
{
    __shared__ float  sF[2 * 232];
    __shared__ float4 sP[2][2][128];   // [k-half][graph][col-quad]
    __shared__ float  sAcc[2];
    const int tid  = threadIdx.x;
    const int g0   = blockIdx.x * 2;
    const int half = tid >> 7;         // k-half: 0 or 1
    const int cq   = tid & 127;        // float4 column group (cols 4cq..4cq+3)

    for (int i = tid; i < 2 * 232; i += 256) sF[i] = g_feat[g0 * 232 + i];
    if (tid < 2) sAcc[tid] = 0.f;
    __syncthreads();

    const float* Wp = W6 + half * 116 * HC;
    const float* f0 = sF + half * 116;          // graph 0, this k-half
    const float* f1 = sF + 232 + half * 116;    // graph 1, this k-half

    float4 a0 = make_float4(0.f, 0.f, 0.f, 0.f);
    float4 a1 = make_float4(0.f, 0.f, 0.f, 0.f);
    #pragma unroll 2
    for (int k = 0; k < 116; k += 4) {
        float4 w0 = ((const float4*)(Wp + (k + 0) * HC))[cq];
        float4 w1 = ((const float4*)(Wp + (k + 1) * HC))[cq];
        float4 w2 = ((const float4*)(Wp + (k + 2) * HC))[cq];
        float4 w3 = ((const float4*)(Wp + (k + 3) * HC))[cq];
        float p00 = f0[k], p01 = f0[k+1], p02 = f0[k+2], p03 = f0[k+3];
        float p10 = f1[k], p11 = f1[k+1], p12 = f1[k+2], p13 = f1[k+3];
        a0.x = fmaf(p00, w0.x, a0.x); a0.y = fmaf(p00, w0.y, a0.y);
        a0.z = fmaf(p00, w0.z, a0.z); a0.w = fmaf(p00, w0.w, a0.w);
        a1.x = fmaf(p10, w0.x, a1.x); a1.y = fmaf(p10, w0.y, a1.y);
        a1.z = fmaf(p10, w0.z, a1.z); a1.w = fmaf(p10, w0.w, a1.w);
        a0.x = fmaf(p01, w1.x, a0.x); a0.y = fmaf(p01, w1.y, a0.y);
        a0.z = fmaf(p01, w1.z, a0.z); a0.w = fmaf(p01, w1.w, a0.w);
        a1.x = fmaf(p11, w1.x, a1.x); a1.y = fmaf(p11, w1.y, a1.y);
        a1.z = fmaf(p11, w1.z, a1.z); a1.w = fmaf(p11, w1.w, a1.w);
        a0.x = fmaf(p02, w2.x, a0.x); a0.y = fmaf(p02, w2.y, a0.y);
        a0.z = fmaf(p02, w2.z, a0.z); a0.w = fmaf(p02, w2.w, a0.w);
        a1.x = fmaf(p12, w2.x, a1.x); a1.y = fmaf(p12, w2.y, a1.y);
        a1.z = fmaf(p12, w2.z, a1.z); a1.w = fmaf(p12, w2.w, a1.w);
        a0.x = fmaf(p03, w3.x, a0.x); a0.y = fmaf(p03, w3.y, a0.y);
        a0.z = fmaf(p03, w3.z, a0.z); a0.w = fmaf(p03, w3.w, a0.w);
        a1.x = fmaf(p13, w3.x, a1.x); a1.y = fmaf(p13, w3.y, a1.y);
        a1.z = fmaf(p13, w3.z, a1.z); a1.w = fmaf(p13, w3.w, a1.w);
    }
    sP[half][0][cq] = a0;
    sP[half][1][cq] = a1;
    __syncthreads();

    // combine halves: thread handles (graph = half, col-quad = cq)
    float4 s0 = sP[0][half][cq];
    float4 s1 = sP[1][half][cq];
    float4 bv = ((const float4*)b6)[cq];
    float4 wv = ((const float4*)W7)[cq];
    float h0 = fmaxf(s0.x + s1.x + bv.x, 0.f);
    float h1 = fmaxf(s0.y + s1.y + bv.y, 0.f);
    float h2 = fmaxf(s0.z + s1.z + bv.z, 0.f);
    float h3 = fmaxf(s0.w + s1.w + bv.w, 0.f);
    float p = fmaf(h0, wv.x, fmaf(h1, wv.y, fmaf(h2, wv.z, h3 * wv.w)));
    #pragma unroll
    for (int o = 16; o; o >>= 1) p += __shfl_xor_sync(0xffffffffu, p, o);
    if ((tid & 31) == 0) atomicAdd(&sAcc[half], p);
    __syncthreads();
    if (tid < 2) out[g0 + tid] = sAcc[tid] + b7[0];
}

extern "C" void kernel_launch(void* const* d_in, const int* in_sizes, int n_in,
                              void* d_out, int out_size)
{
    const float* x  = (const float*)d_in[0];
    const int*   ei = (const int*)  d_in[1];
    const float* ew = (const float*)d_in[2];
    // d_in[3] = batch (unused)
    const float* W1 = (const float*)d_in[4];
    const float* b1 = (const float*)d_in[5];
    const float* W2 = (const float*)d_in[6];
    const float* b2 = (const float*)d_in[7];
    const float* W6 = (const float*)d_in[8];
    const float* b6 = (const float*)d_in[9];
    const float* W7 = (const float*)d_in[10];
    const float* b7 = (const float*)d_in[11];

    cudaFuncSetAttribute(gcn_kernel, cudaFuncAttributeMaxDynamicSharedMemorySize, SMEM_BYTES);

    gcn_kernel<<<2 * NB, 256, SMEM_BYTES>>>(x, ei, ew, W1, b1, W2, b2);
    mlp_kernel<<<NB / 2, 256>>>(W6, b6, W7, b7, (float*)d_out);
}

// round 5
// speedup vs baseline: 1.5577x; 1.0401x over previous
#include <cuda_runtime.h>

#define NB     256
#define NODES  116
#define FEAT   115
#define HID    128
#define LENN   6670
#define SEG2   13456
#define HC     512

#define STRS   132     // S row stride (132 % 32 == 4 -> conflict-free A-frag LDS)
#define STRH   136     // H row stride (136 % 32 == 8 -> conflict-free B-frag LDS)
#define STRW   136     // W row stride

// smem layout (floats)
#define OFF_S    0                    // 128*132 = 16896
#define OFF_H    16896                // 128*136 = 17408
#define OFF_W    34304                // 120*136 = 16320
#define OFF_DINV 50624                // 128
#define SM_FLOATS 50752
#define SMEM_BYTES (SM_FLOATS * 4)    // 203008 B

__device__ float g_feat[NB * 2 * NODES];   // [256][232]

__device__ __forceinline__ unsigned tf32_hi(float f) {
    unsigned r; asm("cvt.rna.tf32.f32 %0, %1;" : "=r"(r) : "f"(f)); return r;
}

__device__ __forceinline__ void mma8(float4& d,
                                     unsigned a0, unsigned a1, unsigned a2, unsigned a3,
                                     unsigned b0, unsigned b1) {
    asm("mma.sync.aligned.m16n8k8.row.col.f32.tf32.tf32.f32 "
        "{%0,%1,%2,%3},{%4,%5,%6,%7},{%8,%9},{%0,%1,%2,%3};"
        : "+f"(d.x), "+f"(d.y), "+f"(d.z), "+f"(d.w)
        : "r"(a0), "r"(a1), "r"(a2), "r"(a3), "r"(b0), "r"(b1));
}

// split a into hi (exact tf32) + lo (residual, truncated by HW on mma read)
#define SPLIT4(ah0,ah1,ah2,ah3, al0,al1,al2,al3, f0,f1,f2,f3)              \
    ah0 = tf32_hi(f0); ah1 = tf32_hi(f1); ah2 = tf32_hi(f2); ah3 = tf32_hi(f3); \
    al0 = __float_as_uint(f0 - __uint_as_float(ah0));                      \
    al1 = __float_as_uint(f1 - __uint_as_float(ah1));                      \
    al2 = __float_as_uint(f2 - __uint_as_float(ah2));                      \
    al3 = __float_as_uint(f3 - __uint_as_float(ah3));

__global__ void __launch_bounds__(256, 1)
gcn_kernel(const float* __restrict__ x,
           const int*   __restrict__ ei,
           const float* __restrict__ ew,
           const float* __restrict__ W1, const float* __restrict__ b1,
           const float* __restrict__ W2, const float* __restrict__ b2)
{
    extern __shared__ float sm[];
    float* sS    = sm + OFF_S;
    float* sH    = sm + OFF_H;
    float* sW    = sm + OFF_W;
    float* sDinv = sm + OFF_DINV;

    const int g    = blockIdx.x >> 1;
    const int v    = blockIdx.x & 1;
    const int tid  = threadIdx.x;
    const int wid  = tid >> 5;
    const int lane = tid & 31;

    const float* W  = v ? W2 : W1;
    const float* bb = v ? b2 : b1;
    const float4 z4 = make_float4(0.f, 0.f, 0.f, 0.f);

    // fragment geometry (fixed per thread)
    const int gr = lane >> 2;          // group id 0..7
    const int c0 = lane & 3;           // thread-in-group 0..3
    const int r0 = 16 * wid + gr;      // first owned output row
    const int r1 = r0 + 8;             // second owned output row

    // ---- Phase 0: zero S, zero+fill W ----
    for (int i = tid; i < (128 * STRS) / 4; i += 256) ((float4*)sS)[i] = z4;
    for (int i = tid; i < (120 * STRW) / 4; i += 256) ((float4*)sW)[i] = z4;
    __syncthreads();
    for (int i = tid; i < FEAT * HID; i += 256) {
        int r = i >> 7;
        int c = i & 127;
        sW[r * STRW + c] = W[i];
    }
    __syncthreads();

    // ---- Phase A: H = X @ W (3xTF32 mma; A streamed from global) ----
    {
        const float* xg  = x + (size_t)(g * (2 * NODES) + v * NODES) * FEAT;
        const float* xr0 = xg + r0 * FEAT;
        const float* xr1 = xg + r1 * FEAT;
        const bool r0ok = r0 < NODES;
        const bool r1ok = r1 < NODES;

        float4 acc[16];
        #pragma unroll
        for (int n = 0; n < 16; n++) acc[n] = z4;

        // prefetched A fragment values (kb = 0: cols c0, c0+4 < 115 always)
        float f0 = r0ok ? xr0[c0]     : 0.f;
        float f1 = r1ok ? xr1[c0]     : 0.f;
        float f2 = r0ok ? xr0[c0 + 4] : 0.f;
        float f3 = r1ok ? xr1[c0 + 4] : 0.f;

        #pragma unroll 1
        for (int kb = 0; kb < 15; kb++) {
            // prefetch next k-block's A values
            float n0 = 0.f, n1 = 0.f, n2 = 0.f, n3 = 0.f;
            if (kb < 14) {
                int ca = 8 * (kb + 1) + c0;
                int cb = ca + 4;
                if (r0ok && ca < FEAT) n0 = xr0[ca];
                if (r1ok && ca < FEAT) n1 = xr1[ca];
                if (r0ok && cb < FEAT) n2 = xr0[cb];
                if (r1ok && cb < FEAT) n3 = xr1[cb];
            }
            unsigned ah0, ah1, ah2, ah3, al0, al1, al2, al3;
            SPLIT4(ah0, ah1, ah2, ah3, al0, al1, al2, al3, f0, f1, f2, f3);

            const float* wb = sW + (8 * kb + c0) * STRW + gr;
            #pragma unroll
            for (int n = 0; n < 16; n++) {
                float b0f = wb[8 * n];
                float b1f = wb[4 * STRW + 8 * n];
                unsigned bh0 = tf32_hi(b0f);
                unsigned bh1 = tf32_hi(b1f);
                unsigned bl0 = __float_as_uint(b0f - __uint_as_float(bh0));
                unsigned bl1 = __float_as_uint(b1f - __uint_as_float(bh1));
                mma8(acc[n], ah0, ah1, ah2, ah3, bl0, bl1);
                mma8(acc[n], al0, al1, al2, al3, bh0, bh1);
                mma8(acc[n], ah0, ah1, ah2, ah3, bh0, bh1);
            }
            f0 = n0; f1 = n1; f2 = n2; f3 = n3;
        }
        // store H rows (pad rows >=116 are exact zeros via guarded A loads)
        #pragma unroll
        for (int n = 0; n < 16; n++) {
            *(float2*)(sH + r0 * STRH + 8 * n + 2 * c0) = make_float2(acc[n].x, acc[n].y);
            *(float2*)(sH + r1 * STRH + 8 * n + 2 * c0) = make_float2(acc[n].z, acc[n].w);
        }
    }

    // ---- Phase 1: scatter edges into S[dst][src] ----
    {
        const int ebase = g * SEG2 + v * LENN;
        const int off   = g * (2 * NODES) + v * NODES;
        const int*   eis = ei + ebase;
        const int*   eid = ei + (NB * SEG2) + ebase;
        const float* ewp = ew + ebase;
        #pragma unroll 2
        for (int e = tid; e < LENN; e += 256) {
            int s = eis[e] - off;
            int d = eid[e] - off;
            atomicAdd(&sS[d * STRS + s], ewp[e]);
        }
    }
    __syncthreads();

    // ---- Phase 2: dinv[i] = rsqrt(rowsum(S[i]) + 1) ----
    for (int r = wid; r < NODES; r += 8) {
        float s = sS[r * STRS + lane]
                + sS[r * STRS + 32 + lane]
                + sS[r * STRS + 64 + lane];
        if (lane < NODES - 96) s += sS[r * STRS + 96 + lane];
        #pragma unroll
        for (int o = 16; o; o >>= 1) s += __shfl_xor_sync(0xffffffffu, s, o);
        if (lane == 0) sDinv[r] = rsqrtf(s + 1.0f);
    }
    __syncthreads();

    // ---- Phase 3: H'[j] = dinv[j] * H[j]  (cols 0..127) ----
    for (int idx = tid; idx < NODES * 32; idx += 256) {
        int r = idx >> 5;
        int q = idx & 31;
        float4 h = ((float4*)(sH + r * STRH))[q];
        float  d = sDinv[r];
        h.x *= d; h.y *= d; h.z *= d; h.w *= d;
        ((float4*)(sH + r * STRH))[q] = h;
    }
    __syncthreads();

    // ---- Phase B: out_i = dinv_i * (S0[i]·H' + H'[i]) + b, channel-max ----
    {
        float4 acc[16];
        #pragma unroll
        for (int n = 0; n < 16; n++) acc[n] = z4;

        const float* sa0 = sS + r0 * STRS;
        const float* sa1 = sS + (r0 + 8) * STRS;

        #pragma unroll 1
        for (int kb = 0; kb < 15; kb++) {
            int kc = 8 * kb + c0;
            float f0 = sa0[kc];
            float f1 = sa1[kc];
            float f2 = sa0[kc + 4];
            float f3 = sa1[kc + 4];
            unsigned ah0, ah1, ah2, ah3, al0, al1, al2, al3;
            SPLIT4(ah0, ah1, ah2, ah3, al0, al1, al2, al3, f0, f1, f2, f3);

            const float* hb = sH + (8 * kb + c0) * STRH + gr;
            #pragma unroll
            for (int n = 0; n < 16; n++) {
                float b0f = hb[8 * n];
                float b1f = hb[4 * STRH + 8 * n];
                unsigned bh0 = tf32_hi(b0f);
                unsigned bh1 = tf32_hi(b1f);
                unsigned bl0 = __float_as_uint(b0f - __uint_as_float(bh0));
                unsigned bl1 = __float_as_uint(b1f - __uint_as_float(bh1));
                mma8(acc[n], ah0, ah1, ah2, ah3, bl0, bl1);
                mma8(acc[n], al0, al1, al2, al3, bh0, bh1);
                mma8(acc[n], ah0, ah1, ah2, ah3, bh0, bh1);
            }
        }

        // epilogue: self-loop term + dinv scale + bias, fused channel-max
        float dv0 = sDinv[r0];
        float dv1 = (r1 < 128) ? sDinv[r1] : 0.f;
        float m0 = -3.0e38f, m1 = -3.0e38f;
        #pragma unroll
        for (int n = 0; n < 16; n++) {
            float2 sh0 = *(float2*)(sH + r0 * STRH + 8 * n + 2 * c0);
            float2 sh1 = *(float2*)(sH + r1 * STRH + 8 * n + 2 * c0);
            float2 bv  = *(const float2*)(bb + 8 * n + 2 * c0);
            float v00 = fmaf(dv0, acc[n].x + sh0.x, bv.x);
            float v01 = fmaf(dv0, acc[n].y + sh0.y, bv.y);
            float v10 = fmaf(dv1, acc[n].z + sh1.x, bv.x);
            float v11 = fmaf(dv1, acc[n].w + sh1.y, bv.y);
            m0 = fmaxf(m0, fmaxf(v00, v01));
            m1 = fmaxf(m1, fmaxf(v10, v11));
        }
        m0 = fmaxf(m0, __shfl_xor_sync(0xffffffffu, m0, 1));
        m0 = fmaxf(m0, __shfl_xor_sync(0xffffffffu, m0, 2));
        m1 = fmaxf(m1, __shfl_xor_sync(0xffffffffu, m1, 1));
        m1 = fmaxf(m1, __shfl_xor_sync(0xffffffffu, m1, 2));
        if (c0 == 0) {
            float* gout = g_feat + g * (2 * NODES) + v;
            if (r0 < NODES) gout[2 * r0] = m0;
            if (r1 < NODES) gout[2 * r1] = m1;
        }
    }
}

// ---- MLP: out[g] = relu(feat[g] @ W6 + b6) @ W7 + b7 ----
// 256 CTAs x 1 graph; 2-way K split x 128 col-quads; float4 LDG batched.
__global__ void __launch_bounds__(256, 1)
mlp_kernel(const float* __restrict__ W6, const float* __restrict__ b6,
           const float* __restrict__ W7, const float* __restrict__ b7,
           float* __restrict__ out)
{
    __shared__ float  sF[232];
    __shared__ float4 sP[2][128];
    __shared__ float  sAcc;
    const int tid  = threadIdx.x;
    const int g    = blockIdx.x;
    const int half = tid >> 7;
    const int cq   = tid & 127;

    for (int i = tid; i < 232; i += 256) sF[i] = g_feat[g * 232 + i];
    if (tid == 0) sAcc = 0.f;
    __syncthreads();

    const float* Wp = W6 + half * 116 * HC;
    const float* fp = sF + half * 116;

    float4 acc = make_float4(0.f, 0.f, 0.f, 0.f);
    #pragma unroll 2
    for (int k = 0; k < 116; k += 4) {
        float4 w0 = ((const float4*)(Wp + (k + 0) * HC))[cq];
        float4 w1 = ((const float4*)(Wp + (k + 1) * HC))[cq];
        float4 w2 = ((const float4*)(Wp + (k + 2) * HC))[cq];
        float4 w3 = ((const float4*)(Wp + (k + 3) * HC))[cq];
        float p0 = fp[k], p1 = fp[k + 1], p2 = fp[k + 2], p3 = fp[k + 3];
        acc.x = fmaf(p0, w0.x, acc.x); acc.y = fmaf(p0, w0.y, acc.y);
        acc.z = fmaf(p0, w0.z, acc.z); acc.w = fmaf(p0, w0.w, acc.w);
        acc.x = fmaf(p1, w1.x, acc.x); acc.y = fmaf(p1, w1.y, acc.y);
        acc.z = fmaf(p1, w1.z, acc.z); acc.w = fmaf(p1, w1.w, acc.w);
        acc.x = fmaf(p2, w2.x, acc.x); acc.y = fmaf(p2, w2.y, acc.y);
        acc.z = fmaf(p2, w2.z, acc.z); acc.w = fmaf(p2, w2.w, acc.w);
        acc.x = fmaf(p3, w3.x, acc.x); acc.y = fmaf(p3, w3.y, acc.y);
        acc.z = fmaf(p3, w3.z, acc.z); acc.w = fmaf(p3, w3.w, acc.w);
    }
    sP[half][cq] = acc;
    __syncthreads();

    if (tid < 128) {
        float4 s0 = sP[0][tid];
        float4 s1 = sP[1][tid];
        float4 bv = ((const float4*)b6)[tid];
        float4 wv = ((const float4*)W7)[tid];
        float h0 = fmaxf(s0.x + s1.x + bv.x, 0.f);
        float h1 = fmaxf(s0.y + s1.y + bv.y, 0.f);
        float h2 = fmaxf(s0.z + s1.z + bv.z, 0.f);
        float h3 = fmaxf(s0.w + s1.w + bv.w, 0.f);
        float p = fmaf(h0, wv.x, fmaf(h1, wv.y, fmaf(h2, wv.z, h3 * wv.w)));
        #pragma unroll
        for (int o = 16; o; o >>= 1) p += __shfl_xor_sync(0xffffffffu, p, o);
        if ((tid & 31) == 0) atomicAdd(&sAcc, p);
    }
    __syncthreads();
    if (tid == 0) out[g] = sAcc + b7[0];
}

extern "C" void kernel_launch(void* const* d_in, const int* in_sizes, int n_in,
                              void* d_out, int out_size)
{
    const float* x  = (const float*)d_in[0];
    const int*   ei = (const int*)  d_in[1];
    const float* ew = (const float*)d_in[2];
    // d_in[3] = batch (unused)
    const float* W1 = (const float*)d_in[4];
    const float* b1 = (const float*)d_in[5];
    const float* W2 = (const float*)d_in[6];
    const float* b2 = (const float*)d_in[7];
    const float* W6 = (const float*)d_in[8];
    const float* b6 = (const float*)d_in[9];
    const float* W7 = (const float*)d_in[10];
    const float* b7 = (const float*)d_in[11];

    cudaFuncSetAttribute(gcn_kernel, cudaFuncAttributeMaxDynamicSharedMemorySize, SMEM_BYTES);

    gcn_kernel<<<2 * NB, 256, SMEM_BYTES>>>(x, ei, ew, W1, b1, W2, b2);
    mlp_kernel<<<NB, 256>>>(W6, b6, W7, b7, (float*)d_out);
}

// round 7
// speedup vs baseline: 1.7779x; 1.1414x over previous
#include <cuda_runtime.h>
#include <cuda_bf16.h>
#include <cstdint>

#define NB     256
#define NODES  116
#define FEAT   115
#define HID    128
#define LENN   6670
#define SEG2   13456
#define HC     512
#define STRS   120         // fp32 S row stride (floats)
#define STRE   136         // bf16 matrix row stride (elements); 272B -> ldmatrix conflict-free

// smem byte offsets (all 16B aligned)
#define OFF_XAH  0                 // A hi  [128][136] bf16 = 34816 B  (X, later S0+I)
#define OFF_XAL  34816             // A lo
#define OFF_WBH  69632             // B hi  [128][136] bf16            (W as [n][k], later H' as [n][k])
#define OFF_WBL  104448            // B lo
#define OFF_S    139264            // fp32 S 116x120 = 55680 B (later reused as sMax)
#define OFF_DINV 194944            // 128 floats
#define OFF_BIAS 195456            // 128 floats
#define SMEM_BYTES 195968

__device__ float g_feat[NB * 2 * NODES];   // [256][232]

static __device__ __forceinline__ uint32_t smem_u32(const void* p) {
    uint32_t a;
    asm("{ .reg .u64 t; cvta.to.shared.u64 t, %1; cvt.u32.u64 %0, t; }" : "=r"(a) : "l"(p));
    return a;
}
static __device__ __forceinline__ void ldsm4(uint32_t& r0, uint32_t& r1, uint32_t& r2, uint32_t& r3,
                                             uint32_t a) {
    asm volatile("ldmatrix.sync.aligned.m8n8.x4.shared.b16 {%0,%1,%2,%3}, [%4];"
                 : "=r"(r0), "=r"(r1), "=r"(r2), "=r"(r3) : "r"(a));
}
static __device__ __forceinline__ void mma_bf16(float4& d,
                                                uint32_t a0, uint32_t a1, uint32_t a2, uint32_t a3,
                                                uint32_t b0, uint32_t b1) {
    asm volatile("mma.sync.aligned.m16n8k16.row.col.f32.bf16.bf16.f32 "
                 "{%0,%1,%2,%3},{%4,%5,%6,%7},{%8,%9},{%0,%1,%2,%3};"
                 : "+f"(d.x), "+f"(d.y), "+f"(d.z), "+f"(d.w)
                 : "r"(a0), "r"(a1), "r"(a2), "r"(a3), "r"(b0), "r"(b1));
}
static __device__ __forceinline__ void split_store(char* smc, uint32_t eoff, float f) {
    __nv_bfloat16 hi = __float2bfloat16(f);
    __nv_bfloat16 lo = __float2bfloat16(f - __bfloat162float(hi));
    *(__nv_bfloat16*)(smc + OFF_XAH + eoff) = hi;   // offsets patched by caller via eoff base
    *(__nv_bfloat16*)(smc + OFF_XAL + eoff) = lo;
}
static __device__ __forceinline__ void split_storeB(char* smc, uint32_t eoff, float f) {
    __nv_bfloat16 hi = __float2bfloat16(f);
    __nv_bfloat16 lo = __float2bfloat16(f - __bfloat162float(hi));
    *(__nv_bfloat16*)(smc + OFF_WBH + eoff) = hi;
    *(__nv_bfloat16*)(smc + OFF_WBL + eoff) = lo;
}

// one 128x128x128 GEMM, 3-pass bf16 split, warp tile = 32 rows x 64 cols
static __device__ __forceinline__ void gemm128(uint32_t aH, uint32_t aL,
                                               uint32_t bH, uint32_t bL,
                                               float4 (&acc)[2][8],
                                               int wm, int wn, int lane)
{
    const int arow = 32 * wm + (lane & 7) + 8 * ((lane >> 3) & 1);
    const int acol = 8 * (lane >> 4);
    const int brow = 64 * wn + 8 * (lane >> 4) + (lane & 7);
    const int bcol = 8 * ((lane >> 3) & 1);

    #pragma unroll 1
    for (int kb = 0; kb < 8; kb++) {
        uint32_t Ah[2][4], Al[2][4];
        #pragma unroll
        for (int mi = 0; mi < 2; mi++) {
            uint32_t offA = (uint32_t)((arow + 16 * mi) * STRE + 16 * kb + acol) * 2;
            ldsm4(Ah[mi][0], Ah[mi][1], Ah[mi][2], Ah[mi][3], aH + offA);
            ldsm4(Al[mi][0], Al[mi][1], Al[mi][2], Al[mi][3], aL + offA);
        }
        #pragma unroll
        for (int j = 0; j < 4; j++) {
            uint32_t offB = (uint32_t)((brow + 16 * j) * STRE + 16 * kb + bcol) * 2;
            uint32_t bh0, bh1, bh2, bh3, bl0, bl1, bl2, bl3;
            ldsm4(bh0, bh1, bh2, bh3, bH + offB);
            ldsm4(bl0, bl1, bl2, bl3, bL + offB);
            #pragma unroll
            for (int mi = 0; mi < 2; mi++) {
                mma_bf16(acc[mi][2*j],   Ah[mi][0], Ah[mi][1], Ah[mi][2], Ah[mi][3], bl0, bl1);
                mma_bf16(acc[mi][2*j],   Al[mi][0], Al[mi][1], Al[mi][2], Al[mi][3], bh0, bh1);
                mma_bf16(acc[mi][2*j],   Ah[mi][0], Ah[mi][1], Ah[mi][2], Ah[mi][3], bh0, bh1);
                mma_bf16(acc[mi][2*j+1], Ah[mi][0], Ah[mi][1], Ah[mi][2], Ah[mi][3], bl2, bl3);
                mma_bf16(acc[mi][2*j+1], Al[mi][0], Al[mi][1], Al[mi][2], Al[mi][3], bh2, bh3);
                mma_bf16(acc[mi][2*j+1], Ah[mi][0], Ah[mi][1], Ah[mi][2], Ah[mi][3], bh2, bh3);
            }
        }
    }
}

__global__ void __launch_bounds__(256, 1)
gcn_kernel(const float* __restrict__ x,
           const int*   __restrict__ ei,
           const float* __restrict__ ew,
           const float* __restrict__ W1, const float* __restrict__ b1,
           const float* __restrict__ W2, const float* __restrict__ b2)
{
    extern __shared__ char smc[];
    float* sS    = (float*)(smc + OFF_S);
    float* sDinv = (float*)(smc + OFF_DINV);
    float* sBias = (float*)(smc + OFF_BIAS);

    const int g    = blockIdx.x >> 1;
    const int v    = blockIdx.x & 1;
    const int tid  = threadIdx.x;
    const int wid  = tid >> 5;
    const int lane = tid & 31;
    const int wm   = wid & 3;       // m-tile: rows 32*wm .. +31
    const int wn   = wid >> 2;      // n-half: cols 64*wn .. +63

    const float* W   = v ? W2 : W1;
    const float* bbp = v ? b2 : b1;
    const float4 z4  = make_float4(0.f, 0.f, 0.f, 0.f);

    // ---- Phase 0: zero bf16 buffers + S; stage bias ----
    for (int i = tid; i < 139264 / 16; i += 256) ((float4*)smc)[i] = z4;
    for (int i = tid; i < 55680 / 16; i += 256) ((float4*)(smc + OFF_S))[i] = z4;
    if (tid < 128) sBias[tid] = bbp[tid];
    __syncthreads();

    // ---- Phase 1: stage X -> A (hi/lo), W -> B as [n][k]; scatter edges ----
    {
        const float* xg = x + (size_t)(g * (2 * NODES) + v * NODES) * FEAT;
        for (int i = tid; i < NODES * FEAT; i += 256) {
            int r = i / FEAT;
            int c = i - r * FEAT;
            split_store(smc, (uint32_t)(r * STRE + c) * 2, xg[i]);
        }
        for (int i = tid; i < FEAT * HID; i += 256) {
            int k = i >> 7;
            int n = i & 127;
            split_storeB(smc, (uint32_t)(n * STRE + k) * 2, W[i]);
        }
        const int ebase = g * SEG2 + v * LENN;
        const int off   = g * (2 * NODES) + v * NODES;
        const int*   eis = ei + ebase;
        const int*   eid = ei + (NB * SEG2) + ebase;
        const float* ewp = ew + ebase;
        #pragma unroll 2
        for (int e = tid; e < LENN; e += 256) {
            int s = eis[e] - off;
            int d = eid[e] - off;
            atomicAdd(&sS[d * STRS + s], ewp[e]);
        }
    }
    __syncthreads();

    // ---- Phase 2: dinv[r] = rsqrt(rowsum(S0)+1); rows>=116 -> 1 ----
    for (int r = wid; r < 128; r += 8) {
        float dv = 1.0f;
        if (r < NODES) {
            float s = sS[r * STRS + lane]
                    + sS[r * STRS + 32 + lane]
                    + sS[r * STRS + 64 + lane];
            if (lane < 24) s += sS[r * STRS + 96 + lane];
            #pragma unroll
            for (int o = 16; o; o >>= 1) s += __shfl_xor_sync(0xffffffffu, s, o);
            dv = rsqrtf(s + 1.0f);
        }
        if (lane == 0) sDinv[r] = dv;
    }
    __syncthreads();

    const uint32_t sb = smem_u32(smc);
    const uint32_t aH = sb + OFF_XAH, aL = sb + OFF_XAL;
    const uint32_t bH = sb + OFF_WBH, bL = sb + OFF_WBL;
    const int gr = lane >> 2;
    const int t2 = (lane & 3) * 2;

    // ---- Phase 3: GEMM1  H = X @ W ----
    float4 acc[2][8];
    #pragma unroll
    for (int mi = 0; mi < 2; mi++)
        #pragma unroll
        for (int nt = 0; nt < 8; nt++) acc[mi][nt] = z4;
    gemm128(aH, aL, bH, bL, acc, wm, wn, lane);
    __syncthreads();    // all reads of X/W buffers complete

    // ---- Phase 4: H' = dinv*H -> B buffers ([n=channel][k=node]);  S0+I -> A ----
    #pragma unroll
    for (int mi = 0; mi < 2; mi++) {
        int r0 = 32 * wm + 16 * mi + gr;
        int r1 = r0 + 8;
        float dv0 = sDinv[r0], dv1 = sDinv[r1];
        #pragma unroll
        for (int nt = 0; nt < 8; nt++) {
            int c0 = 64 * wn + 8 * nt + t2;
            float4 a = acc[mi][nt];
            split_storeB(smc, (uint32_t)( c0      * STRE + r0) * 2, a.x * dv0);
            split_storeB(smc, (uint32_t)((c0 + 1) * STRE + r0) * 2, a.y * dv0);
            split_storeB(smc, (uint32_t)( c0      * STRE + r1) * 2, a.z * dv1);
            split_storeB(smc, (uint32_t)((c0 + 1) * STRE + r1) * 2, a.w * dv1);
        }
    }
    for (int i = tid; i < 128 * 128; i += 256) {
        int r = i >> 7;
        int c = i & 127;
        float val = 0.f;
        if (r < NODES && c < NODES) {
            val = sS[r * STRS + c];
            if (r == c) val += 1.0f;
        }
        split_store(smc, (uint32_t)(r * STRE + c) * 2, val);
    }
    __syncthreads();

    // ---- Phase 5: GEMM2  out = (S0+I) @ H'; epilogue dinv_r*acc + b, channel-max ----
    #pragma unroll
    for (int mi = 0; mi < 2; mi++)
        #pragma unroll
        for (int nt = 0; nt < 8; nt++) acc[mi][nt] = z4;
    gemm128(aH, aL, bH, bL, acc, wm, wn, lane);

    float* sMax = sS;   // reuse: [128][2]
    #pragma unroll
    for (int mi = 0; mi < 2; mi++) {
        int r0 = 32 * wm + 16 * mi + gr;
        int r1 = r0 + 8;
        float dv0 = sDinv[r0], dv1 = sDinv[r1];
        float m0 = -3.0e38f, m1 = -3.0e38f;
        #pragma unroll
        for (int nt = 0; nt < 8; nt++) {
            int c0 = 64 * wn + 8 * nt + t2;
            float b0 = sBias[c0], b1 = sBias[c0 + 1];
            float4 a = acc[mi][nt];
            m0 = fmaxf(m0, fmaxf(fmaf(dv0, a.x, b0), fmaf(dv0, a.y, b1)));
            m1 = fmaxf(m1, fmaxf(fmaf(dv1, a.z, b0), fmaf(dv1, a.w, b1)));
        }
        m0 = fmaxf(m0, __shfl_xor_sync(0xffffffffu, m0, 1));
        m0 = fmaxf(m0, __shfl_xor_sync(0xffffffffu, m0, 2));
        m1 = fmaxf(m1, __shfl_xor_sync(0xffffffffu, m1, 1));
        m1 = fmaxf(m1, __shfl_xor_sync(0xffffffffu, m1, 2));
        if ((lane & 3) == 0) {
            sMax[2 * r0 + wn] = m0;
            sMax[2 * r1 + wn] = m1;
        }
    }
    __syncthreads();
    for (int r = tid; r < NODES; r += 256)
        g_feat[g * 232 + v + 2 * r] = fmaxf(sMax[2 * r], sMax[2 * r + 1]);
}

// ---- MLP: out[g] = relu(feat[g] @ W6 + b6) @ W7 + b7  (R5 version) ----
__global__ void __launch_bounds__(256, 1)
mlp_kernel(const float* __restrict__ W6, const float* __restrict__ b6,
           const float* __restrict__ W7, const float* __restrict__ b7,
           float* __restrict__ out)
{
    __shared__ float  sF[232];
    __shared__ float4 sP[2][128];
    __shared__ float  sAcc;
    const int tid  = threadIdx.x;
    const int g    = blockIdx.x;
    const int half = tid >> 7;
    const int cq   = tid & 127;

    for (int i = tid; i < 232; i += 256) sF[i] = g_feat[g * 232 + i];
    if (tid == 0) sAcc = 0.f;
    __syncthreads();

    const float* Wp = W6 + half * 116 * HC;
    const float* fp = sF + half * 116;

    float4 acc = make_float4(0.f, 0.f, 0.f, 0.f);
    #pragma unroll 2
    for (int k = 0; k < 116; k += 4) {
        float4 w0 = ((const float4*)(Wp + (k + 0) * HC))[cq];
        float4 w1 = ((const float4*)(Wp + (k + 1) * HC))[cq];
        float4 w2 = ((const float4*)(Wp + (k + 2) * HC))[cq];
        float4 w3 = ((const float4*)(Wp + (k + 3) * HC))[cq];
        float p0 = fp[k], p1 = fp[k + 1], p2 = fp[k + 2], p3 = fp[k + 3];
        acc.x = fmaf(p0, w0.x, acc.x); acc.y = fmaf(p0, w0.y, acc.y);
        acc.z = fmaf(p0, w0.z, acc.z); acc.w = fmaf(p0, w0.w, acc.w);
        acc.x = fmaf(p1, w1.x, acc.x); acc.y = fmaf(p1, w1.y, acc.y);
        acc.z = fmaf(p1, w1.z, acc.z); acc.w = fmaf(p1, w1.w, acc.w);
        acc.x = fmaf(p2, w2.x, acc.x); acc.y = fmaf(p2, w2.y, acc.y);
        acc.z = fmaf(p2, w2.z, acc.z); acc.w = fmaf(p2, w2.w, acc.w);
        acc.x = fmaf(p3, w3.x, acc.x); acc.y = fmaf(p3, w3.y, acc.y);
        acc.z = fmaf(p3, w3.z, acc.z); acc.w = fmaf(p3, w3.w, acc.w);
    }
    sP[half][cq] = acc;
    __syncthreads();

    if (tid < 128) {
        float4 s0 = sP[0][tid];
        float4 s1 = sP[1][tid];
        float4 bv = ((const float4*)b6)[tid];
        float4 wv = ((const float4*)W7)[tid];
        float h0 = fmaxf(s0.x + s1.x + bv.x, 0.f);
        float h1 = fmaxf(s0.y + s1.y + bv.y, 0.f);
        float h2 = fmaxf(s0.z + s1.z + bv.z, 0.f);
        float h3 = fmaxf(s0.w + s1.w + bv.w, 0.f);
        float p = fmaf(h0, wv.x, fmaf(h1, wv.y, fmaf(h2, wv.z, h3 * wv.w)));
        #pragma unroll
        for (int o = 16; o; o >>= 1) p += __shfl_xor_sync(0xffffffffu, p, o);
        if ((tid & 31) == 0) atomicAdd(&sAcc, p);
    }
    __syncthreads();
    if (tid == 0) out[g] = sAcc + b7[0];
}

extern "C" void kernel_launch(void* const* d_in, const int* in_sizes, int n_in,
                              void* d_out, int out_size)
{
    const float* x  = (const float*)d_in[0];
    const int*   ei = (const int*)  d_in[1];
    const float* ew = (const float*)d_in[2];
    // d_in[3] = batch (unused)
    const float* W1 = (const float*)d_in[4];
    const float* b1 = (const float*)d_in[5];
    const float* W2 = (const float*)d_in[6];
    const float* b2 = (const float*)d_in[7];
    const float* W6 = (const float*)d_in[8];
    const float* b6 = (const float*)d_in[9];
    const float* W7 = (const float*)d_in[10];
    const float* b7 = (const float*)d_in[11];

    cudaFuncSetAttribute(gcn_kernel, cudaFuncAttributeMaxDynamicSharedMemorySize, SMEM_BYTES);

    gcn_kernel<<<2 * NB, 256, SMEM_BYTES>>>(x, ei, ew, W1, b1, W2, b2);
    mlp_kernel<<<NB, 256>>>(W6, b6, W7, b7, (float*)d_out);
}